// round 14
// baseline (speedup 1.0000x reference)
#include <cuda_runtime.h>
#include <cstdint>

#define N_MAX  100000
#define E_MAX  1600000
#define F_IN   256
#define F_H    128
#define F_OUT  40

// ---------------- device scratch (static globals: no allocation at launch) ----------------
static __device__ int   g_deg_src[N_MAX];
static __device__ int   g_deg_dst[N_MAX];
static __device__ float g_out_isqrt[N_MAX];
static __device__ float g_in_isqrt[N_MAX];
static __device__ int   g_row_ptr[N_MAX + 1];
static __device__ int   g_cursor[N_MAX];
static __device__ int   g_col[E_MAX];
static __device__ __align__(16) float g_h1[(size_t)N_MAX * F_H];   // (X@W1)*out_isqrt
static __device__ __align__(16) float g_m1[(size_t)N_MAX * F_H];   // relu(agg1*in_isqrt + b1)
static __device__ __align__(16) float g_h2[(size_t)N_MAX * F_OUT]; // (m1@W2)*out_isqrt

// ---------------- setup kernels ----------------
__global__ void k_zero(int n) {
    int i = blockIdx.x * blockDim.x + threadIdx.x;
    if (i < n) { g_deg_src[i] = 0; g_deg_dst[i] = 0; }
}

__global__ void k_degree(const int* __restrict__ src, const int* __restrict__ dst, int e) {
    int i = blockIdx.x * blockDim.x + threadIdx.x;
    if (i < e) {
        atomicAdd(&g_deg_src[src[i]], 1);
        atomicAdd(&g_deg_dst[dst[i]], 1);
    }
}

__global__ void k_norm(int n) {
    int i = blockIdx.x * blockDim.x + threadIdx.x;
    if (i < n) {
        g_out_isqrt[i] = rsqrtf(fmaxf((float)g_deg_src[i], 1.0f));
        g_in_isqrt[i]  = rsqrtf(fmaxf((float)g_deg_dst[i], 1.0f));
    }
}

// Single-block exclusive scan of g_deg_dst -> g_row_ptr (n+1), copy into g_cursor.
__global__ void k_scan(int n) {
    __shared__ int wsum[32];
    const int t    = threadIdx.x;           // 1024 threads
    const int per  = (n + 1023) / 1024;
    const int lane = t & 31, wid = t >> 5;
    int start = t * per;
    int end   = start + per; if (end > n) end = n; if (start > n) start = n;

    int s = 0;
    for (int i = start; i < end; ++i) s += g_deg_dst[i];

    // inclusive scan of per-thread sums
    int v = s;
    #pragma unroll
    for (int o = 1; o < 32; o <<= 1) { int u = __shfl_up_sync(~0u, v, o); if (lane >= o) v += u; }
    if (lane == 31) wsum[wid] = v;
    __syncthreads();
    if (wid == 0) {
        int w = wsum[lane];
        #pragma unroll
        for (int o = 1; o < 32; o <<= 1) { int u = __shfl_up_sync(~0u, w, o); if (lane >= o) w += u; }
        wsum[lane] = w;
    }
    __syncthreads();
    int excl = v - s + (wid ? wsum[wid - 1] : 0);

    int run = excl;
    for (int i = start; i < end; ++i) {
        g_row_ptr[i] = run;
        g_cursor[i]  = run;
        run += g_deg_dst[i];
    }
    if (t == 1023) g_row_ptr[n] = excl + s;  // total == E
}

__global__ void k_fill(const int* __restrict__ src, const int* __restrict__ dst, int e) {
    int i = blockIdx.x * blockDim.x + threadIdx.x;
    if (i < e) {
        int p = atomicAdd(&g_cursor[dst[i]], 1);
        g_col[p] = src[i];
    }
}

// ---------------- GEMM1: h1 = (X @ W1) * out_isqrt ----------------
// 128 threads, 64 rows x 128 cols per block, 8x8 register tile per thread, K chunked by 32.
__global__ void k_gemm1(const float* __restrict__ X, const float* __restrict__ W1, int n) {
    __shared__ float Xs[64][33];
    __shared__ float Ws[32][128];
    const int t = threadIdx.x;             // 0..127
    const int rowbase = blockIdx.x * 64;
    const int rg = t >> 4;                 // 0..7  -> rows rg*8..+7
    const int cg = t & 15;                 // 0..15 -> cols cg*8..+7

    float acc[8][8];
    #pragma unroll
    for (int i = 0; i < 8; i++)
        #pragma unroll
        for (int j = 0; j < 8; j++) acc[i][j] = 0.f;

    for (int c = 0; c < F_IN / 32; ++c) {
        #pragma unroll
        for (int i = 0; i < 4; i++) {
            int idx = t + 128 * i;         // 0..511 float4 slots
            int r = idx >> 3, kv = idx & 7;
            int gr = rowbase + r; if (gr >= n) gr = n - 1;
            float4 v = *(const float4*)(X + (size_t)gr * F_IN + c * 32 + kv * 4);
            Xs[r][kv * 4 + 0] = v.x; Xs[r][kv * 4 + 1] = v.y;
            Xs[r][kv * 4 + 2] = v.z; Xs[r][kv * 4 + 3] = v.w;
        }
        #pragma unroll
        for (int i = 0; i < 8; i++) {
            int idx = t + 128 * i;         // 0..1023 float4 slots
            int r = idx >> 5, cv = idx & 31;
            float4 v = *(const float4*)(W1 + (size_t)(c * 32 + r) * F_H + cv * 4);
            *(float4*)&Ws[r][cv * 4] = v;
        }
        __syncthreads();

        #pragma unroll 8
        for (int kk = 0; kk < 32; kk++) {
            float a[8];
            #pragma unroll
            for (int i = 0; i < 8; i++) a[i] = Xs[rg * 8 + i][kk];
            float4 b0 = *(const float4*)&Ws[kk][cg * 8];
            float4 b1 = *(const float4*)&Ws[kk][cg * 8 + 4];
            #pragma unroll
            for (int i = 0; i < 8; i++) {
                acc[i][0] = fmaf(a[i], b0.x, acc[i][0]);
                acc[i][1] = fmaf(a[i], b0.y, acc[i][1]);
                acc[i][2] = fmaf(a[i], b0.z, acc[i][2]);
                acc[i][3] = fmaf(a[i], b0.w, acc[i][3]);
                acc[i][4] = fmaf(a[i], b1.x, acc[i][4]);
                acc[i][5] = fmaf(a[i], b1.y, acc[i][5]);
                acc[i][6] = fmaf(a[i], b1.z, acc[i][6]);
                acc[i][7] = fmaf(a[i], b1.w, acc[i][7]);
            }
        }
        __syncthreads();
    }

    #pragma unroll
    for (int i = 0; i < 8; i++) {
        int gr = rowbase + rg * 8 + i;
        if (gr < n) {
            float s = g_out_isqrt[gr];
            float4 o0 = make_float4(acc[i][0] * s, acc[i][1] * s, acc[i][2] * s, acc[i][3] * s);
            float4 o1 = make_float4(acc[i][4] * s, acc[i][5] * s, acc[i][6] * s, acc[i][7] * s);
            *(float4*)(g_h1 + (size_t)gr * F_H + cg * 8)     = o0;
            *(float4*)(g_h1 + (size_t)gr * F_H + cg * 8 + 4) = o1;
        }
    }
}

// ---------------- AGG1: m1 = relu(in_isqrt * sum_{s in N(dst)} h1[s] + b1) ----------------
// one warp per dst node; lane owns 4 contiguous floats (float4) of the 128-dim row.
__global__ void k_agg1(const float* __restrict__ b1, int n) {
    int gw = (blockIdx.x * blockDim.x + threadIdx.x) >> 5;
    if (gw >= n) return;
    int lane = threadIdx.x & 31;
    int beg = g_row_ptr[gw], end = g_row_ptr[gw + 1];

    float4 a0 = make_float4(0.f, 0.f, 0.f, 0.f);
    float4 a1 = make_float4(0.f, 0.f, 0.f, 0.f);
    int e = beg;
    for (; e + 2 <= end; e += 2) {
        int s0 = g_col[e], s1 = g_col[e + 1];
        float4 v0 = *((const float4*)(g_h1 + (size_t)s0 * F_H) + lane);
        float4 v1 = *((const float4*)(g_h1 + (size_t)s1 * F_H) + lane);
        a0.x += v0.x; a0.y += v0.y; a0.z += v0.z; a0.w += v0.w;
        a1.x += v1.x; a1.y += v1.y; a1.z += v1.z; a1.w += v1.w;
    }
    if (e < end) {
        int s0 = g_col[e];
        float4 v0 = *((const float4*)(g_h1 + (size_t)s0 * F_H) + lane);
        a0.x += v0.x; a0.y += v0.y; a0.z += v0.z; a0.w += v0.w;
    }
    float sc = g_in_isqrt[gw];
    float4 bb = ((const float4*)b1)[lane];
    float4 o;
    o.x = fmaxf(fmaf(a0.x + a1.x, sc, bb.x), 0.f);
    o.y = fmaxf(fmaf(a0.y + a1.y, sc, bb.y), 0.f);
    o.z = fmaxf(fmaf(a0.z + a1.z, sc, bb.z), 0.f);
    o.w = fmaxf(fmaf(a0.w + a1.w, sc, bb.w), 0.f);
    *((float4*)(g_m1 + (size_t)gw * F_H) + lane) = o;
}

// ---------------- GEMM2: h2 = (m1 @ W2) * out_isqrt ----------------
// 128 threads, 64 rows x 40 cols per block, 4x5 register tile, K chunked by 64.
__global__ void k_gemm2(const float* __restrict__ W2, int n) {
    __shared__ float Xs[64][65];
    __shared__ float Ws[64][F_OUT];
    const int t = threadIdx.x;             // 0..127
    const int rowbase = blockIdx.x * 64;
    const int rg = t >> 3;                 // 0..15 -> rows rg*4..+3
    const int cg = t & 7;                  // 0..7  -> cols cg*5..+4

    float acc[4][5];
    #pragma unroll
    for (int i = 0; i < 4; i++)
        #pragma unroll
        for (int j = 0; j < 5; j++) acc[i][j] = 0.f;

    for (int c = 0; c < 2; ++c) {
        #pragma unroll
        for (int i = 0; i < 8; i++) {
            int idx = t + 128 * i;         // 0..1023 float4 slots
            int r = idx >> 4, kv = idx & 15;
            int gr = rowbase + r; if (gr >= n) gr = n - 1;
            float4 v = *(const float4*)(g_m1 + (size_t)gr * F_H + c * 64 + kv * 4);
            Xs[r][kv * 4 + 0] = v.x; Xs[r][kv * 4 + 1] = v.y;
            Xs[r][kv * 4 + 2] = v.z; Xs[r][kv * 4 + 3] = v.w;
        }
        #pragma unroll
        for (int i = 0; i < 20; i++) {
            int idx = t + 128 * i;         // 0..2559
            int r = idx / F_OUT;
            int cc = idx - r * F_OUT;
            Ws[r][cc] = W2[(size_t)(c * 64 + r) * F_OUT + cc];
        }
        __syncthreads();

        #pragma unroll 8
        for (int kk = 0; kk < 64; kk++) {
            float a[4];
            #pragma unroll
            for (int i = 0; i < 4; i++) a[i] = Xs[rg * 4 + i][kk];
            float b[5];
            #pragma unroll
            for (int j = 0; j < 5; j++) b[j] = Ws[kk][cg * 5 + j];
            #pragma unroll
            for (int i = 0; i < 4; i++)
                #pragma unroll
                for (int j = 0; j < 5; j++) acc[i][j] = fmaf(a[i], b[j], acc[i][j]);
        }
        __syncthreads();
    }

    #pragma unroll
    for (int i = 0; i < 4; i++) {
        int gr = rowbase + rg * 4 + i;
        if (gr < n) {
            float s = g_out_isqrt[gr];
            #pragma unroll
            for (int j = 0; j < 5; j++)
                g_h2[(size_t)gr * F_OUT + cg * 5 + j] = acc[i][j] * s;
        }
    }
}

// ---------------- AGG2: out = in_isqrt * sum h2[s] + b2 ----------------
// one warp per dst node; lane owns feature `lane`, lanes 0..7 also own 32+lane.
__global__ void k_agg2(const float* __restrict__ b2, float* __restrict__ out, int n) {
    int gw = (blockIdx.x * blockDim.x + threadIdx.x) >> 5;
    if (gw >= n) return;
    int lane = threadIdx.x & 31;
    int beg = g_row_ptr[gw], end = g_row_ptr[gw + 1];
    bool hi = lane < (F_OUT - 32);

    float a0 = 0.f, a1 = 0.f, c0 = 0.f, c1 = 0.f;
    int e = beg;
    for (; e + 2 <= end; e += 2) {
        int s0 = g_col[e], s1 = g_col[e + 1];
        const float* r0 = g_h2 + (size_t)s0 * F_OUT;
        const float* r1 = g_h2 + (size_t)s1 * F_OUT;
        a0 += r0[lane];
        c0 += r1[lane];
        if (hi) { a1 += r0[32 + lane]; c1 += r1[32 + lane]; }
    }
    if (e < end) {
        const float* r0 = g_h2 + (size_t)g_col[e] * F_OUT;
        a0 += r0[lane];
        if (hi) a1 += r0[32 + lane];
    }
    float sc = g_in_isqrt[gw];
    out[(size_t)gw * F_OUT + lane] = fmaf(a0 + c0, sc, b2[lane]);
    if (hi)
        out[(size_t)gw * F_OUT + 32 + lane] = fmaf(a1 + c1, sc, b2[32 + lane]);
}

// ---------------- launch ----------------
extern "C" void kernel_launch(void* const* d_in, const int* in_sizes, int n_in,
                              void* d_out, int out_size) {
    const float* X   = (const float*)d_in[0];
    const int*   src = (const int*)d_in[1];
    const int*   dst = (const int*)d_in[2];
    const float* W1  = (const float*)d_in[3];
    const float* b1  = (const float*)d_in[4];
    const float* W2  = (const float*)d_in[5];
    const float* b2  = (const float*)d_in[6];
    float* out = (float*)d_out;

    const int Nn = in_sizes[0] / F_IN;   // 100000
    const int E  = in_sizes[1];          // 1600000

    k_zero  <<<(Nn + 255) / 256, 256>>>(Nn);
    k_degree<<<(E  + 255) / 256, 256>>>(src, dst, E);
    k_norm  <<<(Nn + 255) / 256, 256>>>(Nn);
    k_scan  <<<1, 1024>>>(Nn);
    k_fill  <<<(E  + 255) / 256, 256>>>(src, dst, E);

    k_gemm1 <<<(Nn + 63) / 64, 128>>>(X, W1, Nn);
    k_agg1  <<<((size_t)Nn * 32 + 255) / 256, 256>>>(b1, Nn);
    k_gemm2 <<<(Nn + 63) / 64, 128>>>(W2, Nn);
    k_agg2  <<<((size_t)Nn * 32 + 255) / 256, 256>>>(b2, out, Nn);
}

// round 15
// speedup vs baseline: 1.0014x; 1.0014x over previous
#include <cuda_runtime.h>
#include <cstdint>

#define N_MAX  100000
#define E_MAX  1600000
#define F_IN   256
#define F_H    128
#define F_OUT  40

// ---------------- device scratch (static globals: no allocation at launch) ----------------
static __device__ int   g_deg_src[N_MAX];
static __device__ int   g_deg_dst[N_MAX];
static __device__ float g_out_isqrt[N_MAX];
static __device__ float g_in_isqrt[N_MAX];
static __device__ int   g_row_ptr[N_MAX + 1];
static __device__ int   g_cursor[N_MAX];
static __device__ int   g_col[E_MAX];
static __device__ __align__(16) float g_h1[(size_t)N_MAX * F_H];   // (X@W1)*out_isqrt
static __device__ __align__(16) float g_m1[(size_t)N_MAX * F_H];   // relu(agg1*in_isqrt + b1)
static __device__ __align__(16) float g_h2[(size_t)N_MAX * F_OUT]; // (m1@W2)*out_isqrt

// ---------------- setup kernels ----------------
__global__ void k_zero(int n) {
    int i = blockIdx.x * blockDim.x + threadIdx.x;
    if (i < n) { g_deg_src[i] = 0; g_deg_dst[i] = 0; }
}

__global__ void k_degree(const int* __restrict__ src, const int* __restrict__ dst, int e) {
    int i = blockIdx.x * blockDim.x + threadIdx.x;
    if (i < e) {
        atomicAdd(&g_deg_src[src[i]], 1);
        atomicAdd(&g_deg_dst[dst[i]], 1);
    }
}

__global__ void k_norm(int n) {
    int i = blockIdx.x * blockDim.x + threadIdx.x;
    if (i < n) {
        g_out_isqrt[i] = rsqrtf(fmaxf((float)g_deg_src[i], 1.0f));
        g_in_isqrt[i]  = rsqrtf(fmaxf((float)g_deg_dst[i], 1.0f));
    }
}

// Single-block exclusive scan of g_deg_dst -> g_row_ptr (n+1), copy into g_cursor.
__global__ void k_scan(int n) {
    __shared__ int wsum[32];
    const int t    = threadIdx.x;           // 1024 threads
    const int per  = (n + 1023) / 1024;
    const int lane = t & 31, wid = t >> 5;
    int start = t * per;
    int end   = start + per; if (end > n) end = n; if (start > n) start = n;

    int s = 0;
    for (int i = start; i < end; ++i) s += g_deg_dst[i];

    // inclusive scan of per-thread sums
    int v = s;
    #pragma unroll
    for (int o = 1; o < 32; o <<= 1) { int u = __shfl_up_sync(~0u, v, o); if (lane >= o) v += u; }
    if (lane == 31) wsum[wid] = v;
    __syncthreads();
    if (wid == 0) {
        int w = wsum[lane];
        #pragma unroll
        for (int o = 1; o < 32; o <<= 1) { int u = __shfl_up_sync(~0u, w, o); if (lane >= o) w += u; }
        wsum[lane] = w;
    }
    __syncthreads();
    int excl = v - s + (wid ? wsum[wid - 1] : 0);

    int run = excl;
    for (int i = start; i < end; ++i) {
        g_row_ptr[i] = run;
        g_cursor[i]  = run;
        run += g_deg_dst[i];
    }
    if (t == 1023) g_row_ptr[n] = excl + s;  // total == E
}

__global__ void k_fill(const int* __restrict__ src, const int* __restrict__ dst, int e) {
    int i = blockIdx.x * blockDim.x + threadIdx.x;
    if (i < e) {
        int p = atomicAdd(&g_cursor[dst[i]], 1);
        g_col[p] = src[i];
    }
}

// ---------------- GEMM1: h1 = (X @ W1) * out_isqrt ----------------
// 128 threads, 64 rows x 128 cols per block, 8x8 register tile per thread, K chunked by 32.
__global__ void k_gemm1(const float* __restrict__ X, const float* __restrict__ W1, int n) {
    __shared__ float Xs[64][33];
    __shared__ float Ws[32][128];
    const int t = threadIdx.x;             // 0..127
    const int rowbase = blockIdx.x * 64;
    const int rg = t >> 4;                 // 0..7  -> rows rg*8..+7
    const int cg = t & 15;                 // 0..15 -> cols cg*8..+7

    float acc[8][8];
    #pragma unroll
    for (int i = 0; i < 8; i++)
        #pragma unroll
        for (int j = 0; j < 8; j++) acc[i][j] = 0.f;

    for (int c = 0; c < F_IN / 32; ++c) {
        #pragma unroll
        for (int i = 0; i < 4; i++) {
            int idx = t + 128 * i;         // 0..511 float4 slots
            int r = idx >> 3, kv = idx & 7;
            int gr = rowbase + r; if (gr >= n) gr = n - 1;
            float4 v = *(const float4*)(X + (size_t)gr * F_IN + c * 32 + kv * 4);
            Xs[r][kv * 4 + 0] = v.x; Xs[r][kv * 4 + 1] = v.y;
            Xs[r][kv * 4 + 2] = v.z; Xs[r][kv * 4 + 3] = v.w;
        }
        #pragma unroll
        for (int i = 0; i < 8; i++) {
            int idx = t + 128 * i;         // 0..1023 float4 slots
            int r = idx >> 5, cv = idx & 31;
            float4 v = *(const float4*)(W1 + (size_t)(c * 32 + r) * F_H + cv * 4);
            *(float4*)&Ws[r][cv * 4] = v;
        }
        __syncthreads();

        #pragma unroll 8
        for (int kk = 0; kk < 32; kk++) {
            float a[8];
            #pragma unroll
            for (int i = 0; i < 8; i++) a[i] = Xs[rg * 8 + i][kk];
            float4 b0 = *(const float4*)&Ws[kk][cg * 8];
            float4 b1 = *(const float4*)&Ws[kk][cg * 8 + 4];
            #pragma unroll
            for (int i = 0; i < 8; i++) {
                acc[i][0] = fmaf(a[i], b0.x, acc[i][0]);
                acc[i][1] = fmaf(a[i], b0.y, acc[i][1]);
                acc[i][2] = fmaf(a[i], b0.z, acc[i][2]);
                acc[i][3] = fmaf(a[i], b0.w, acc[i][3]);
                acc[i][4] = fmaf(a[i], b1.x, acc[i][4]);
                acc[i][5] = fmaf(a[i], b1.y, acc[i][5]);
                acc[i][6] = fmaf(a[i], b1.z, acc[i][6]);
                acc[i][7] = fmaf(a[i], b1.w, acc[i][7]);
            }
        }
        __syncthreads();
    }

    #pragma unroll
    for (int i = 0; i < 8; i++) {
        int gr = rowbase + rg * 8 + i;
        if (gr < n) {
            float s = g_out_isqrt[gr];
            float4 o0 = make_float4(acc[i][0] * s, acc[i][1] * s, acc[i][2] * s, acc[i][3] * s);
            float4 o1 = make_float4(acc[i][4] * s, acc[i][5] * s, acc[i][6] * s, acc[i][7] * s);
            *(float4*)(g_h1 + (size_t)gr * F_H + cg * 8)     = o0;
            *(float4*)(g_h1 + (size_t)gr * F_H + cg * 8 + 4) = o1;
        }
    }
}

// ---------------- AGG1: m1 = relu(in_isqrt * sum_{s in N(dst)} h1[s] + b1) ----------------
// one warp per dst node; lane owns 4 contiguous floats (float4) of the 128-dim row.
__global__ void k_agg1(const float* __restrict__ b1, int n) {
    int gw = (blockIdx.x * blockDim.x + threadIdx.x) >> 5;
    if (gw >= n) return;
    int lane = threadIdx.x & 31;
    int beg = g_row_ptr[gw], end = g_row_ptr[gw + 1];

    float4 a0 = make_float4(0.f, 0.f, 0.f, 0.f);
    float4 a1 = make_float4(0.f, 0.f, 0.f, 0.f);
    int e = beg;
    for (; e + 2 <= end; e += 2) {
        int s0 = g_col[e], s1 = g_col[e + 1];
        float4 v0 = *((const float4*)(g_h1 + (size_t)s0 * F_H) + lane);
        float4 v1 = *((const float4*)(g_h1 + (size_t)s1 * F_H) + lane);
        a0.x += v0.x; a0.y += v0.y; a0.z += v0.z; a0.w += v0.w;
        a1.x += v1.x; a1.y += v1.y; a1.z += v1.z; a1.w += v1.w;
    }
    if (e < end) {
        int s0 = g_col[e];
        float4 v0 = *((const float4*)(g_h1 + (size_t)s0 * F_H) + lane);
        a0.x += v0.x; a0.y += v0.y; a0.z += v0.z; a0.w += v0.w;
    }
    float sc = g_in_isqrt[gw];
    float4 bb = ((const float4*)b1)[lane];
    float4 o;
    o.x = fmaxf(fmaf(a0.x + a1.x, sc, bb.x), 0.f);
    o.y = fmaxf(fmaf(a0.y + a1.y, sc, bb.y), 0.f);
    o.z = fmaxf(fmaf(a0.z + a1.z, sc, bb.z), 0.f);
    o.w = fmaxf(fmaf(a0.w + a1.w, sc, bb.w), 0.f);
    *((float4*)(g_m1 + (size_t)gw * F_H) + lane) = o;
}

// ---------------- GEMM2: h2 = (m1 @ W2) * out_isqrt ----------------
// 128 threads, 64 rows x 40 cols per block, 4x5 register tile, K chunked by 64.
__global__ void k_gemm2(const float* __restrict__ W2, int n) {
    __shared__ float Xs[64][65];
    __shared__ float Ws[64][F_OUT];
    const int t = threadIdx.x;             // 0..127
    const int rowbase = blockIdx.x * 64;
    const int rg = t >> 3;                 // 0..15 -> rows rg*4..+3
    const int cg = t & 7;                  // 0..7  -> cols cg*5..+4

    float acc[4][5];
    #pragma unroll
    for (int i = 0; i < 4; i++)
        #pragma unroll
        for (int j = 0; j < 5; j++) acc[i][j] = 0.f;

    for (int c = 0; c < 2; ++c) {
        #pragma unroll
        for (int i = 0; i < 8; i++) {
            int idx = t + 128 * i;         // 0..1023 float4 slots
            int r = idx >> 4, kv = idx & 15;
            int gr = rowbase + r; if (gr >= n) gr = n - 1;
            float4 v = *(const float4*)(g_m1 + (size_t)gr * F_H + c * 64 + kv * 4);
            Xs[r][kv * 4 + 0] = v.x; Xs[r][kv * 4 + 1] = v.y;
            Xs[r][kv * 4 + 2] = v.z; Xs[r][kv * 4 + 3] = v.w;
        }
        #pragma unroll
        for (int i = 0; i < 20; i++) {
            int idx = t + 128 * i;         // 0..2559
            int r = idx / F_OUT;
            int cc = idx - r * F_OUT;
            Ws[r][cc] = W2[(size_t)(c * 64 + r) * F_OUT + cc];
        }
        __syncthreads();

        #pragma unroll 8
        for (int kk = 0; kk < 64; kk++) {
            float a[4];
            #pragma unroll
            for (int i = 0; i < 4; i++) a[i] = Xs[rg * 4 + i][kk];
            float b[5];
            #pragma unroll
            for (int j = 0; j < 5; j++) b[j] = Ws[kk][cg * 5 + j];
            #pragma unroll
            for (int i = 0; i < 4; i++)
                #pragma unroll
                for (int j = 0; j < 5; j++) acc[i][j] = fmaf(a[i], b[j], acc[i][j]);
        }
        __syncthreads();
    }

    #pragma unroll
    for (int i = 0; i < 4; i++) {
        int gr = rowbase + rg * 4 + i;
        if (gr < n) {
            float s = g_out_isqrt[gr];
            #pragma unroll
            for (int j = 0; j < 5; j++)
                g_h2[(size_t)gr * F_OUT + cg * 5 + j] = acc[i][j] * s;
        }
    }
}

// ---------------- AGG2: out = in_isqrt * sum h2[s] + b2 ----------------
// one warp per dst node; lane owns feature `lane`, lanes 0..7 also own 32+lane.
__global__ void k_agg2(const float* __restrict__ b2, float* __restrict__ out, int n) {
    int gw = (blockIdx.x * blockDim.x + threadIdx.x) >> 5;
    if (gw >= n) return;
    int lane = threadIdx.x & 31;
    int beg = g_row_ptr[gw], end = g_row_ptr[gw + 1];
    bool hi = lane < (F_OUT - 32);

    float a0 = 0.f, a1 = 0.f, c0 = 0.f, c1 = 0.f;
    int e = beg;
    for (; e + 2 <= end; e += 2) {
        int s0 = g_col[e], s1 = g_col[e + 1];
        const float* r0 = g_h2 + (size_t)s0 * F_OUT;
        const float* r1 = g_h2 + (size_t)s1 * F_OUT;
        a0 += r0[lane];
        c0 += r1[lane];
        if (hi) { a1 += r0[32 + lane]; c1 += r1[32 + lane]; }
    }
    if (e < end) {
        const float* r0 = g_h2 + (size_t)g_col[e] * F_OUT;
        a0 += r0[lane];
        if (hi) a1 += r0[32 + lane];
    }
    float sc = g_in_isqrt[gw];
    out[(size_t)gw * F_OUT + lane] = fmaf(a0 + c0, sc, b2[lane]);
    if (hi)
        out[(size_t)gw * F_OUT + 32 + lane] = fmaf(a1 + c1, sc, b2[32 + lane]);
}

// ---------------- launch ----------------
extern "C" void kernel_launch(void* const* d_in, const int* in_sizes, int n_in,
                              void* d_out, int out_size) {
    const float* X   = (const float*)d_in[0];
    const int*   src = (const int*)d_in[1];
    const int*   dst = (const int*)d_in[2];
    const float* W1  = (const float*)d_in[3];
    const float* b1  = (const float*)d_in[4];
    const float* W2  = (const float*)d_in[5];
    const float* b2  = (const float*)d_in[6];
    float* out = (float*)d_out;

    const int Nn = in_sizes[0] / F_IN;   // 100000
    const int E  = in_sizes[1];          // 1600000

    k_zero  <<<(Nn + 255) / 256, 256>>>(Nn);
    k_degree<<<(E  + 255) / 256, 256>>>(src, dst, E);
    k_norm  <<<(Nn + 255) / 256, 256>>>(Nn);
    k_scan  <<<1, 1024>>>(Nn);
    k_fill  <<<(E  + 255) / 256, 256>>>(src, dst, E);

    k_gemm1 <<<(Nn + 63) / 64, 128>>>(X, W1, Nn);
    k_agg1  <<<((size_t)Nn * 32 + 255) / 256, 256>>>(b1, Nn);
    k_gemm2 <<<(Nn + 63) / 64, 128>>>(W2, Nn);
    k_agg2  <<<((size_t)Nn * 32 + 255) / 256, 256>>>(b2, out, Nn);
}

// round 16
// speedup vs baseline: 1.4515x; 1.4495x over previous
#include <cuda_runtime.h>
#include <cstdint>

#define N_MAX  100000
#define E_MAX  1600000
#define F_IN   256
#define F_H    128
#define F_OUT  40

#define SCAN_BLK   1024
#define SCAN_ELEMS 2048   // 2 per thread
#define SCAN_NBMAX 1024

// ---------------- device scratch (static globals: no allocation at launch) ----------------
static __device__ int   g_deg_src[N_MAX];
static __device__ int   g_deg_dst[N_MAX];
static __device__ float g_out_isqrt[N_MAX];
static __device__ float g_in_isqrt[N_MAX];
static __device__ int   g_row_ptr[N_MAX + 1];
static __device__ int   g_cursor[N_MAX];
static __device__ int   g_col[E_MAX];
static __device__ int   g_bsum[SCAN_NBMAX];
static __device__ __align__(16) float g_h1[(size_t)N_MAX * F_H];   // (X@W1)*out_isqrt
static __device__ __align__(16) float g_m1[(size_t)N_MAX * F_H];   // relu(agg1*in_isqrt + b1)
static __device__ __align__(16) float g_h2[(size_t)N_MAX * F_OUT]; // (m1@W2)*out_isqrt

// ---------------- setup kernels ----------------
__global__ void k_zero(int n) {
    int i = blockIdx.x * blockDim.x + threadIdx.x;
    if (i < n) { g_deg_src[i] = 0; g_deg_dst[i] = 0; }
}

__global__ void k_degree(const int* __restrict__ src, const int* __restrict__ dst, int e) {
    int i = blockIdx.x * blockDim.x + threadIdx.x;
    if (i < e) {
        atomicAdd(&g_deg_src[src[i]], 1);
        atomicAdd(&g_deg_dst[dst[i]], 1);
    }
}

__global__ void k_norm(int n) {
    int i = blockIdx.x * blockDim.x + threadIdx.x;
    if (i < n) {
        g_out_isqrt[i] = rsqrtf(fmaxf((float)g_deg_src[i], 1.0f));
        g_in_isqrt[i]  = rsqrtf(fmaxf((float)g_deg_dst[i], 1.0f));
    }
}

// ---------------- 3-phase device-wide exclusive scan of g_deg_dst ----------------
// Phase 1: per-block local exclusive scan (2 elems/thread) -> g_row_ptr (local), block total -> g_bsum.
__global__ void k_scan_local(int n) {
    __shared__ int wsum[32];
    const int t = threadIdx.x, lane = t & 31, wid = t >> 5;
    const int i0 = blockIdx.x * SCAN_ELEMS + t * 2;
    const int i1 = i0 + 1;

    int d0 = (i0 < n) ? g_deg_dst[i0] : 0;
    int d1 = (i1 < n) ? g_deg_dst[i1] : 0;
    int s  = d0 + d1;

    int v = s;  // inclusive scan of per-thread sums
    #pragma unroll
    for (int o = 1; o < 32; o <<= 1) { int u = __shfl_up_sync(~0u, v, o); if (lane >= o) v += u; }
    if (lane == 31) wsum[wid] = v;
    __syncthreads();
    if (wid == 0) {
        int w = wsum[lane];
        #pragma unroll
        for (int o = 1; o < 32; o <<= 1) { int u = __shfl_up_sync(~0u, w, o); if (lane >= o) w += u; }
        wsum[lane] = w;
    }
    __syncthreads();
    int excl = v - s + (wid ? wsum[wid - 1] : 0);

    if (i0 < n) g_row_ptr[i0] = excl;
    if (i1 < n) g_row_ptr[i1] = excl + d0;
    if (t == SCAN_BLK - 1) g_bsum[blockIdx.x] = excl + s;  // block total
}

// Phase 2: one block exclusive-scans the block totals in place (nb <= 1024).
__global__ void k_scan_bsum(int nb) {
    __shared__ int wsum[32];
    const int t = threadIdx.x, lane = t & 31, wid = t >> 5;
    int s = (t < nb) ? g_bsum[t] : 0;
    int v = s;
    #pragma unroll
    for (int o = 1; o < 32; o <<= 1) { int u = __shfl_up_sync(~0u, v, o); if (lane >= o) v += u; }
    if (lane == 31) wsum[wid] = v;
    __syncthreads();
    if (wid == 0) {
        int w = wsum[lane];
        #pragma unroll
        for (int o = 1; o < 32; o <<= 1) { int u = __shfl_up_sync(~0u, w, o); if (lane >= o) w += u; }
        wsum[lane] = w;
    }
    __syncthreads();
    int excl = v - s + (wid ? wsum[wid - 1] : 0);
    if (t < nb) g_bsum[t] = excl;
}

// Phase 3: add block offsets, mirror into cursor, seal row_ptr[n].
__global__ void k_scan_add(int n, int e) {
    int i = blockIdx.x * blockDim.x + threadIdx.x;
    if (i < n) {
        int v = g_row_ptr[i] + g_bsum[i / SCAN_ELEMS];
        g_row_ptr[i] = v;
        g_cursor[i]  = v;
    }
    if (i == 0) g_row_ptr[n] = e;
}

__global__ void k_fill(const int* __restrict__ src, const int* __restrict__ dst, int e) {
    int i = blockIdx.x * blockDim.x + threadIdx.x;
    if (i < e) {
        int p = atomicAdd(&g_cursor[dst[i]], 1);
        g_col[p] = src[i];
    }
}

// ---------------- GEMM1: h1 = (X @ W1) * out_isqrt ----------------
// 128 threads, 64 rows x 128 cols per block, 8x8 register tile per thread, K chunked by 32.
__global__ void k_gemm1(const float* __restrict__ X, const float* __restrict__ W1, int n) {
    __shared__ float Xs[64][33];
    __shared__ float Ws[32][128];
    const int t = threadIdx.x;             // 0..127
    const int rowbase = blockIdx.x * 64;
    const int rg = t >> 4;                 // 0..7  -> rows rg*8..+7
    const int cg = t & 15;                 // 0..15 -> cols cg*8..+7

    float acc[8][8];
    #pragma unroll
    for (int i = 0; i < 8; i++)
        #pragma unroll
        for (int j = 0; j < 8; j++) acc[i][j] = 0.f;

    for (int c = 0; c < F_IN / 32; ++c) {
        #pragma unroll
        for (int i = 0; i < 4; i++) {
            int idx = t + 128 * i;         // 0..511 float4 slots
            int r = idx >> 3, kv = idx & 7;
            int gr = rowbase + r; if (gr >= n) gr = n - 1;
            float4 v = *(const float4*)(X + (size_t)gr * F_IN + c * 32 + kv * 4);
            Xs[r][kv * 4 + 0] = v.x; Xs[r][kv * 4 + 1] = v.y;
            Xs[r][kv * 4 + 2] = v.z; Xs[r][kv * 4 + 3] = v.w;
        }
        #pragma unroll
        for (int i = 0; i < 8; i++) {
            int idx = t + 128 * i;         // 0..1023 float4 slots
            int r = idx >> 5, cv = idx & 31;
            float4 v = *(const float4*)(W1 + (size_t)(c * 32 + r) * F_H + cv * 4);
            *(float4*)&Ws[r][cv * 4] = v;
        }
        __syncthreads();

        #pragma unroll 8
        for (int kk = 0; kk < 32; kk++) {
            float a[8];
            #pragma unroll
            for (int i = 0; i < 8; i++) a[i] = Xs[rg * 8 + i][kk];
            float4 b0 = *(const float4*)&Ws[kk][cg * 8];
            float4 b1 = *(const float4*)&Ws[kk][cg * 8 + 4];
            #pragma unroll
            for (int i = 0; i < 8; i++) {
                acc[i][0] = fmaf(a[i], b0.x, acc[i][0]);
                acc[i][1] = fmaf(a[i], b0.y, acc[i][1]);
                acc[i][2] = fmaf(a[i], b0.z, acc[i][2]);
                acc[i][3] = fmaf(a[i], b0.w, acc[i][3]);
                acc[i][4] = fmaf(a[i], b1.x, acc[i][4]);
                acc[i][5] = fmaf(a[i], b1.y, acc[i][5]);
                acc[i][6] = fmaf(a[i], b1.z, acc[i][6]);
                acc[i][7] = fmaf(a[i], b1.w, acc[i][7]);
            }
        }
        __syncthreads();
    }

    #pragma unroll
    for (int i = 0; i < 8; i++) {
        int gr = rowbase + rg * 8 + i;
        if (gr < n) {
            float s = g_out_isqrt[gr];
            float4 o0 = make_float4(acc[i][0] * s, acc[i][1] * s, acc[i][2] * s, acc[i][3] * s);
            float4 o1 = make_float4(acc[i][4] * s, acc[i][5] * s, acc[i][6] * s, acc[i][7] * s);
            *(float4*)(g_h1 + (size_t)gr * F_H + cg * 8)     = o0;
            *(float4*)(g_h1 + (size_t)gr * F_H + cg * 8 + 4) = o1;
        }
    }
}

// ---------------- AGG1: m1 = relu(in_isqrt * sum_{s in N(dst)} h1[s] + b1) ----------------
// one warp per dst node; lane owns 4 contiguous floats (float4) of the 128-dim row.
__global__ void k_agg1(const float* __restrict__ b1, int n) {
    int gw = (blockIdx.x * blockDim.x + threadIdx.x) >> 5;
    if (gw >= n) return;
    int lane = threadIdx.x & 31;
    int beg = g_row_ptr[gw], end = g_row_ptr[gw + 1];

    float4 a0 = make_float4(0.f, 0.f, 0.f, 0.f);
    float4 a1 = make_float4(0.f, 0.f, 0.f, 0.f);
    int e = beg;
    for (; e + 2 <= end; e += 2) {
        int s0 = g_col[e], s1 = g_col[e + 1];
        float4 v0 = *((const float4*)(g_h1 + (size_t)s0 * F_H) + lane);
        float4 v1 = *((const float4*)(g_h1 + (size_t)s1 * F_H) + lane);
        a0.x += v0.x; a0.y += v0.y; a0.z += v0.z; a0.w += v0.w;
        a1.x += v1.x; a1.y += v1.y; a1.z += v1.z; a1.w += v1.w;
    }
    if (e < end) {
        int s0 = g_col[e];
        float4 v0 = *((const float4*)(g_h1 + (size_t)s0 * F_H) + lane);
        a0.x += v0.x; a0.y += v0.y; a0.z += v0.z; a0.w += v0.w;
    }
    float sc = g_in_isqrt[gw];
    float4 bb = ((const float4*)b1)[lane];
    float4 o;
    o.x = fmaxf(fmaf(a0.x + a1.x, sc, bb.x), 0.f);
    o.y = fmaxf(fmaf(a0.y + a1.y, sc, bb.y), 0.f);
    o.z = fmaxf(fmaf(a0.z + a1.z, sc, bb.z), 0.f);
    o.w = fmaxf(fmaf(a0.w + a1.w, sc, bb.w), 0.f);
    *((float4*)(g_m1 + (size_t)gw * F_H) + lane) = o;
}

// ---------------- GEMM2: h2 = (m1 @ W2) * out_isqrt ----------------
// 128 threads, 64 rows x 40 cols per block, 4x5 register tile, K chunked by 64.
__global__ void k_gemm2(const float* __restrict__ W2, int n) {
    __shared__ float Xs[64][65];
    __shared__ float Ws[64][F_OUT];
    const int t = threadIdx.x;             // 0..127
    const int rowbase = blockIdx.x * 64;
    const int rg = t >> 3;                 // 0..15 -> rows rg*4..+3
    const int cg = t & 7;                  // 0..7  -> cols cg*5..+4

    float acc[4][5];
    #pragma unroll
    for (int i = 0; i < 4; i++)
        #pragma unroll
        for (int j = 0; j < 5; j++) acc[i][j] = 0.f;

    for (int c = 0; c < 2; ++c) {
        #pragma unroll
        for (int i = 0; i < 8; i++) {
            int idx = t + 128 * i;         // 0..1023 float4 slots
            int r = idx >> 4, kv = idx & 15;
            int gr = rowbase + r; if (gr >= n) gr = n - 1;
            float4 v = *(const float4*)(g_m1 + (size_t)gr * F_H + c * 64 + kv * 4);
            Xs[r][kv * 4 + 0] = v.x; Xs[r][kv * 4 + 1] = v.y;
            Xs[r][kv * 4 + 2] = v.z; Xs[r][kv * 4 + 3] = v.w;
        }
        #pragma unroll
        for (int i = 0; i < 20; i++) {
            int idx = t + 128 * i;         // 0..2559
            int r = idx / F_OUT;
            int cc = idx - r * F_OUT;
            Ws[r][cc] = W2[(size_t)(c * 64 + r) * F_OUT + cc];
        }
        __syncthreads();

        #pragma unroll 8
        for (int kk = 0; kk < 64; kk++) {
            float a[4];
            #pragma unroll
            for (int i = 0; i < 4; i++) a[i] = Xs[rg * 4 + i][kk];
            float b[5];
            #pragma unroll
            for (int j = 0; j < 5; j++) b[j] = Ws[kk][cg * 5 + j];
            #pragma unroll
            for (int i = 0; i < 4; i++)
                #pragma unroll
                for (int j = 0; j < 5; j++) acc[i][j] = fmaf(a[i], b[j], acc[i][j]);
        }
        __syncthreads();
    }

    #pragma unroll
    for (int i = 0; i < 4; i++) {
        int gr = rowbase + rg * 4 + i;
        if (gr < n) {
            float s = g_out_isqrt[gr];
            #pragma unroll
            for (int j = 0; j < 5; j++)
                g_h2[(size_t)gr * F_OUT + cg * 5 + j] = acc[i][j] * s;
        }
    }
}

// ---------------- AGG2: out = in_isqrt * sum h2[s] + b2 ----------------
// one warp per dst node; lane owns feature `lane`, lanes 0..7 also own 32+lane.
__global__ void k_agg2(const float* __restrict__ b2, float* __restrict__ out, int n) {
    int gw = (blockIdx.x * blockDim.x + threadIdx.x) >> 5;
    if (gw >= n) return;
    int lane = threadIdx.x & 31;
    int beg = g_row_ptr[gw], end = g_row_ptr[gw + 1];
    bool hi = lane < (F_OUT - 32);

    float a0 = 0.f, a1 = 0.f, c0 = 0.f, c1 = 0.f;
    int e = beg;
    for (; e + 2 <= end; e += 2) {
        int s0 = g_col[e], s1 = g_col[e + 1];
        const float* r0 = g_h2 + (size_t)s0 * F_OUT;
        const float* r1 = g_h2 + (size_t)s1 * F_OUT;
        a0 += r0[lane];
        c0 += r1[lane];
        if (hi) { a1 += r0[32 + lane]; c1 += r1[32 + lane]; }
    }
    if (e < end) {
        const float* r0 = g_h2 + (size_t)g_col[e] * F_OUT;
        a0 += r0[lane];
        if (hi) a1 += r0[32 + lane];
    }
    float sc = g_in_isqrt[gw];
    out[(size_t)gw * F_OUT + lane] = fmaf(a0 + c0, sc, b2[lane]);
    if (hi)
        out[(size_t)gw * F_OUT + 32 + lane] = fmaf(a1 + c1, sc, b2[32 + lane]);
}

// ---------------- launch ----------------
extern "C" void kernel_launch(void* const* d_in, const int* in_sizes, int n_in,
                              void* d_out, int out_size) {
    const float* X   = (const float*)d_in[0];
    const int*   src = (const int*)d_in[1];
    const int*   dst = (const int*)d_in[2];
    const float* W1  = (const float*)d_in[3];
    const float* b1  = (const float*)d_in[4];
    const float* W2  = (const float*)d_in[5];
    const float* b2  = (const float*)d_in[6];
    float* out = (float*)d_out;

    const int Nn = in_sizes[0] / F_IN;   // 100000
    const int E  = in_sizes[1];          // 1600000
    const int nb = (Nn + SCAN_ELEMS - 1) / SCAN_ELEMS;   // 49 blocks

    k_zero      <<<(Nn + 255) / 256, 256>>>(Nn);
    k_degree    <<<(E  + 255) / 256, 256>>>(src, dst, E);
    k_norm      <<<(Nn + 255) / 256, 256>>>(Nn);
    k_scan_local<<<nb, SCAN_BLK>>>(Nn);
    k_scan_bsum <<<1, SCAN_NBMAX>>>(nb);
    k_scan_add  <<<(Nn + 255) / 256, 256>>>(Nn, E);
    k_fill      <<<(E  + 255) / 256, 256>>>(src, dst, E);

    k_gemm1 <<<(Nn + 63) / 64, 128>>>(X, W1, Nn);
    k_agg1  <<<((size_t)Nn * 32 + 255) / 256, 256>>>(b1, Nn);
    k_gemm2 <<<(Nn + 63) / 64, 128>>>(W2, Nn);
    k_agg2  <<<((size_t)Nn * 32 + 255) / 256, 256>>>(b2, out, Nn);
}

// round 17
// speedup vs baseline: 1.4540x; 1.0017x over previous
#include <cuda_runtime.h>
#include <cstdint>

#define N_MAX  100000
#define E_MAX  1600000
#define F_IN   256
#define F_H    128
#define F_OUT  40

#define SCAN_BLK   1024
#define SCAN_ELEMS 2048   // 2 per thread
#define SCAN_NBMAX 1024

// ---------------- device scratch (static globals: no allocation at launch) ----------------
static __device__ int   g_deg_src[N_MAX];
static __device__ int   g_deg_dst[N_MAX];
static __device__ float g_out_isqrt[N_MAX];
static __device__ float g_in_isqrt[N_MAX];
static __device__ int   g_row_ptr[N_MAX + 1];
static __device__ int   g_cursor[N_MAX];
static __device__ int   g_col[E_MAX];
static __device__ int   g_bsum[SCAN_NBMAX];
static __device__ __align__(16) float g_h1[(size_t)N_MAX * F_H];   // (X@W1)*out_isqrt
static __device__ __align__(16) float g_m1[(size_t)N_MAX * F_H];   // relu(agg1*in_isqrt + b1)
static __device__ __align__(16) float g_h2[(size_t)N_MAX * F_OUT]; // (m1@W2)*out_isqrt

// ---------------- setup kernels ----------------
__global__ void k_zero(int n) {
    int i = blockIdx.x * blockDim.x + threadIdx.x;
    if (i < n) { g_deg_src[i] = 0; g_deg_dst[i] = 0; }
}

__global__ void k_degree(const int* __restrict__ src, const int* __restrict__ dst, int e) {
    int i = blockIdx.x * blockDim.x + threadIdx.x;
    if (i < e) {
        atomicAdd(&g_deg_src[src[i]], 1);
        atomicAdd(&g_deg_dst[dst[i]], 1);
    }
}

__global__ void k_norm(int n) {
    int i = blockIdx.x * blockDim.x + threadIdx.x;
    if (i < n) {
        g_out_isqrt[i] = rsqrtf(fmaxf((float)g_deg_src[i], 1.0f));
        g_in_isqrt[i]  = rsqrtf(fmaxf((float)g_deg_dst[i], 1.0f));
    }
}

// ---------------- 3-phase device-wide exclusive scan of g_deg_dst ----------------
// Phase 1: per-block local exclusive scan (2 elems/thread) -> g_row_ptr (local), block total -> g_bsum.
__global__ void k_scan_local(int n) {
    __shared__ int wsum[32];
    const int t = threadIdx.x, lane = t & 31, wid = t >> 5;
    const int i0 = blockIdx.x * SCAN_ELEMS + t * 2;
    const int i1 = i0 + 1;

    int d0 = (i0 < n) ? g_deg_dst[i0] : 0;
    int d1 = (i1 < n) ? g_deg_dst[i1] : 0;
    int s  = d0 + d1;

    int v = s;  // inclusive scan of per-thread sums
    #pragma unroll
    for (int o = 1; o < 32; o <<= 1) { int u = __shfl_up_sync(~0u, v, o); if (lane >= o) v += u; }
    if (lane == 31) wsum[wid] = v;
    __syncthreads();
    if (wid == 0) {
        int w = wsum[lane];
        #pragma unroll
        for (int o = 1; o < 32; o <<= 1) { int u = __shfl_up_sync(~0u, w, o); if (lane >= o) w += u; }
        wsum[lane] = w;
    }
    __syncthreads();
    int excl = v - s + (wid ? wsum[wid - 1] : 0);

    if (i0 < n) g_row_ptr[i0] = excl;
    if (i1 < n) g_row_ptr[i1] = excl + d0;
    if (t == SCAN_BLK - 1) g_bsum[blockIdx.x] = excl + s;  // block total
}

// Phase 2: one block exclusive-scans the block totals in place (nb <= 1024).
__global__ void k_scan_bsum(int nb) {
    __shared__ int wsum[32];
    const int t = threadIdx.x, lane = t & 31, wid = t >> 5;
    int s = (t < nb) ? g_bsum[t] : 0;
    int v = s;
    #pragma unroll
    for (int o = 1; o < 32; o <<= 1) { int u = __shfl_up_sync(~0u, v, o); if (lane >= o) v += u; }
    if (lane == 31) wsum[wid] = v;
    __syncthreads();
    if (wid == 0) {
        int w = wsum[lane];
        #pragma unroll
        for (int o = 1; o < 32; o <<= 1) { int u = __shfl_up_sync(~0u, w, o); if (lane >= o) w += u; }
        wsum[lane] = w;
    }
    __syncthreads();
    int excl = v - s + (wid ? wsum[wid - 1] : 0);
    if (t < nb) g_bsum[t] = excl;
}

// Phase 3: add block offsets, mirror into cursor, seal row_ptr[n].
__global__ void k_scan_add(int n, int e) {
    int i = blockIdx.x * blockDim.x + threadIdx.x;
    if (i < n) {
        int v = g_row_ptr[i] + g_bsum[i / SCAN_ELEMS];
        g_row_ptr[i] = v;
        g_cursor[i]  = v;
    }
    if (i == 0) g_row_ptr[n] = e;
}

__global__ void k_fill(const int* __restrict__ src, const int* __restrict__ dst, int e) {
    int i = blockIdx.x * blockDim.x + threadIdx.x;
    if (i < e) {
        int p = atomicAdd(&g_cursor[dst[i]], 1);
        g_col[p] = src[i];
    }
}

// ---------------- GEMM1: h1 = (X @ W1) * out_isqrt ----------------
// 128 threads, 64 rows x 128 cols per block, 8x8 register tile per thread, K chunked by 32.
__global__ void k_gemm1(const float* __restrict__ X, const float* __restrict__ W1, int n) {
    __shared__ float Xs[64][33];
    __shared__ float Ws[32][128];
    const int t = threadIdx.x;             // 0..127
    const int rowbase = blockIdx.x * 64;
    const int rg = t >> 4;                 // 0..7  -> rows rg*8..+7
    const int cg = t & 15;                 // 0..15 -> cols cg*8..+7

    float acc[8][8];
    #pragma unroll
    for (int i = 0; i < 8; i++)
        #pragma unroll
        for (int j = 0; j < 8; j++) acc[i][j] = 0.f;

    for (int c = 0; c < F_IN / 32; ++c) {
        #pragma unroll
        for (int i = 0; i < 4; i++) {
            int idx = t + 128 * i;         // 0..511 float4 slots
            int r = idx >> 3, kv = idx & 7;
            int gr = rowbase + r; if (gr >= n) gr = n - 1;
            float4 v = *(const float4*)(X + (size_t)gr * F_IN + c * 32 + kv * 4);
            Xs[r][kv * 4 + 0] = v.x; Xs[r][kv * 4 + 1] = v.y;
            Xs[r][kv * 4 + 2] = v.z; Xs[r][kv * 4 + 3] = v.w;
        }
        #pragma unroll
        for (int i = 0; i < 8; i++) {
            int idx = t + 128 * i;         // 0..1023 float4 slots
            int r = idx >> 5, cv = idx & 31;
            float4 v = *(const float4*)(W1 + (size_t)(c * 32 + r) * F_H + cv * 4);
            *(float4*)&Ws[r][cv * 4] = v;
        }
        __syncthreads();

        #pragma unroll 8
        for (int kk = 0; kk < 32; kk++) {
            float a[8];
            #pragma unroll
            for (int i = 0; i < 8; i++) a[i] = Xs[rg * 8 + i][kk];
            float4 b0 = *(const float4*)&Ws[kk][cg * 8];
            float4 b1 = *(const float4*)&Ws[kk][cg * 8 + 4];
            #pragma unroll
            for (int i = 0; i < 8; i++) {
                acc[i][0] = fmaf(a[i], b0.x, acc[i][0]);
                acc[i][1] = fmaf(a[i], b0.y, acc[i][1]);
                acc[i][2] = fmaf(a[i], b0.z, acc[i][2]);
                acc[i][3] = fmaf(a[i], b0.w, acc[i][3]);
                acc[i][4] = fmaf(a[i], b1.x, acc[i][4]);
                acc[i][5] = fmaf(a[i], b1.y, acc[i][5]);
                acc[i][6] = fmaf(a[i], b1.z, acc[i][6]);
                acc[i][7] = fmaf(a[i], b1.w, acc[i][7]);
            }
        }
        __syncthreads();
    }

    #pragma unroll
    for (int i = 0; i < 8; i++) {
        int gr = rowbase + rg * 8 + i;
        if (gr < n) {
            float s = g_out_isqrt[gr];
            float4 o0 = make_float4(acc[i][0] * s, acc[i][1] * s, acc[i][2] * s, acc[i][3] * s);
            float4 o1 = make_float4(acc[i][4] * s, acc[i][5] * s, acc[i][6] * s, acc[i][7] * s);
            *(float4*)(g_h1 + (size_t)gr * F_H + cg * 8)     = o0;
            *(float4*)(g_h1 + (size_t)gr * F_H + cg * 8 + 4) = o1;
        }
    }
}

// ---------------- AGG1: m1 = relu(in_isqrt * sum_{s in N(dst)} h1[s] + b1) ----------------
// one warp per dst node; lane owns 4 contiguous floats (float4) of the 128-dim row.
__global__ void k_agg1(const float* __restrict__ b1, int n) {
    int gw = (blockIdx.x * blockDim.x + threadIdx.x) >> 5;
    if (gw >= n) return;
    int lane = threadIdx.x & 31;
    int beg = g_row_ptr[gw], end = g_row_ptr[gw + 1];

    float4 a0 = make_float4(0.f, 0.f, 0.f, 0.f);
    float4 a1 = make_float4(0.f, 0.f, 0.f, 0.f);
    int e = beg;
    for (; e + 2 <= end; e += 2) {
        int s0 = g_col[e], s1 = g_col[e + 1];
        float4 v0 = *((const float4*)(g_h1 + (size_t)s0 * F_H) + lane);
        float4 v1 = *((const float4*)(g_h1 + (size_t)s1 * F_H) + lane);
        a0.x += v0.x; a0.y += v0.y; a0.z += v0.z; a0.w += v0.w;
        a1.x += v1.x; a1.y += v1.y; a1.z += v1.z; a1.w += v1.w;
    }
    if (e < end) {
        int s0 = g_col[e];
        float4 v0 = *((const float4*)(g_h1 + (size_t)s0 * F_H) + lane);
        a0.x += v0.x; a0.y += v0.y; a0.z += v0.z; a0.w += v0.w;
    }
    float sc = g_in_isqrt[gw];
    float4 bb = ((const float4*)b1)[lane];
    float4 o;
    o.x = fmaxf(fmaf(a0.x + a1.x, sc, bb.x), 0.f);
    o.y = fmaxf(fmaf(a0.y + a1.y, sc, bb.y), 0.f);
    o.z = fmaxf(fmaf(a0.z + a1.z, sc, bb.z), 0.f);
    o.w = fmaxf(fmaf(a0.w + a1.w, sc, bb.w), 0.f);
    *((float4*)(g_m1 + (size_t)gw * F_H) + lane) = o;
}

// ---------------- GEMM2: h2 = (m1 @ W2) * out_isqrt ----------------
// 128 threads, 64 rows x 40 cols per block, 4x5 register tile, K chunked by 64.
__global__ void k_gemm2(const float* __restrict__ W2, int n) {
    __shared__ float Xs[64][65];
    __shared__ float Ws[64][F_OUT];
    const int t = threadIdx.x;             // 0..127
    const int rowbase = blockIdx.x * 64;
    const int rg = t >> 3;                 // 0..15 -> rows rg*4..+3
    const int cg = t & 7;                  // 0..7  -> cols cg*5..+4

    float acc[4][5];
    #pragma unroll
    for (int i = 0; i < 4; i++)
        #pragma unroll
        for (int j = 0; j < 5; j++) acc[i][j] = 0.f;

    for (int c = 0; c < 2; ++c) {
        #pragma unroll
        for (int i = 0; i < 8; i++) {
            int idx = t + 128 * i;         // 0..1023 float4 slots
            int r = idx >> 4, kv = idx & 15;
            int gr = rowbase + r; if (gr >= n) gr = n - 1;
            float4 v = *(const float4*)(g_m1 + (size_t)gr * F_H + c * 64 + kv * 4);
            Xs[r][kv * 4 + 0] = v.x; Xs[r][kv * 4 + 1] = v.y;
            Xs[r][kv * 4 + 2] = v.z; Xs[r][kv * 4 + 3] = v.w;
        }
        #pragma unroll
        for (int i = 0; i < 20; i++) {
            int idx = t + 128 * i;         // 0..2559
            int r = idx / F_OUT;
            int cc = idx - r * F_OUT;
            Ws[r][cc] = W2[(size_t)(c * 64 + r) * F_OUT + cc];
        }
        __syncthreads();

        #pragma unroll 8
        for (int kk = 0; kk < 64; kk++) {
            float a[4];
            #pragma unroll
            for (int i = 0; i < 4; i++) a[i] = Xs[rg * 4 + i][kk];
            float b[5];
            #pragma unroll
            for (int j = 0; j < 5; j++) b[j] = Ws[kk][cg * 5 + j];
            #pragma unroll
            for (int i = 0; i < 4; i++)
                #pragma unroll
                for (int j = 0; j < 5; j++) acc[i][j] = fmaf(a[i], b[j], acc[i][j]);
        }
        __syncthreads();
    }

    #pragma unroll
    for (int i = 0; i < 4; i++) {
        int gr = rowbase + rg * 4 + i;
        if (gr < n) {
            float s = g_out_isqrt[gr];
            #pragma unroll
            for (int j = 0; j < 5; j++)
                g_h2[(size_t)gr * F_OUT + cg * 5 + j] = acc[i][j] * s;
        }
    }
}

// ---------------- AGG2: out = in_isqrt * sum h2[s] + b2 ----------------
// one warp per dst node; lane owns feature `lane`, lanes 0..7 also own 32+lane.
__global__ void k_agg2(const float* __restrict__ b2, float* __restrict__ out, int n) {
    int gw = (blockIdx.x * blockDim.x + threadIdx.x) >> 5;
    if (gw >= n) return;
    int lane = threadIdx.x & 31;
    int beg = g_row_ptr[gw], end = g_row_ptr[gw + 1];
    bool hi = lane < (F_OUT - 32);

    float a0 = 0.f, a1 = 0.f, c0 = 0.f, c1 = 0.f;
    int e = beg;
    for (; e + 2 <= end; e += 2) {
        int s0 = g_col[e], s1 = g_col[e + 1];
        const float* r0 = g_h2 + (size_t)s0 * F_OUT;
        const float* r1 = g_h2 + (size_t)s1 * F_OUT;
        a0 += r0[lane];
        c0 += r1[lane];
        if (hi) { a1 += r0[32 + lane]; c1 += r1[32 + lane]; }
    }
    if (e < end) {
        const float* r0 = g_h2 + (size_t)g_col[e] * F_OUT;
        a0 += r0[lane];
        if (hi) a1 += r0[32 + lane];
    }
    float sc = g_in_isqrt[gw];
    out[(size_t)gw * F_OUT + lane] = fmaf(a0 + c0, sc, b2[lane]);
    if (hi)
        out[(size_t)gw * F_OUT + 32 + lane] = fmaf(a1 + c1, sc, b2[32 + lane]);
}

// ---------------- launch ----------------
extern "C" void kernel_launch(void* const* d_in, const int* in_sizes, int n_in,
                              void* d_out, int out_size) {
    const float* X   = (const float*)d_in[0];
    const int*   src = (const int*)d_in[1];
    const int*   dst = (const int*)d_in[2];
    const float* W1  = (const float*)d_in[3];
    const float* b1  = (const float*)d_in[4];
    const float* W2  = (const float*)d_in[5];
    const float* b2  = (const float*)d_in[6];
    float* out = (float*)d_out;

    const int Nn = in_sizes[0] / F_IN;   // 100000
    const int E  = in_sizes[1];          // 1600000
    const int nb = (Nn + SCAN_ELEMS - 1) / SCAN_ELEMS;   // 49 blocks

    k_zero      <<<(Nn + 255) / 256, 256>>>(Nn);
    k_degree    <<<(E  + 255) / 256, 256>>>(src, dst, E);
    k_norm      <<<(Nn + 255) / 256, 256>>>(Nn);
    k_scan_local<<<nb, SCAN_BLK>>>(Nn);
    k_scan_bsum <<<1, SCAN_NBMAX>>>(nb);
    k_scan_add  <<<(Nn + 255) / 256, 256>>>(Nn, E);
    k_fill      <<<(E  + 255) / 256, 256>>>(src, dst, E);

    k_gemm1 <<<(Nn + 63) / 64, 128>>>(X, W1, Nn);
    k_agg1  <<<((size_t)Nn * 32 + 255) / 256, 256>>>(b1, Nn);
    k_gemm2 <<<(Nn + 63) / 64, 128>>>(W2, Nn);
    k_agg2  <<<((size_t)Nn * 32 + 255) / 256, 256>>>(b2, out, Nn);
}